// round 15
// baseline (speedup 1.0000x reference)
#include <cuda_runtime.h>
#include <cstdint>

#define N_NODES 100000
#define N_EDGES 1250000
#define DIM 64
#define NBASES 16
#define E_HALF (N_EDGES / 2)
#define N_TILES ((N_NODES + 63) / 64)           // 1563
#define GEMM_STRIDE 26                          // every 26th mid block is a GEMM block
#define SCAT_BLOCKS ((E_HALF * 16 + 255) / 256) // 39063
#define MID_BLOCKS (N_TILES + SCAT_BLOCKS)      // 40626 (multiples of 26 in range = 1563)

// ---------------- scratch (device globals; no allocation allowed) ----------
__device__ float g_S[(size_t)N_NODES * DIM];    // scatter-sum; self-zeroed by final_kernel
__device__ float g_Xs[(size_t)N_NODES * DIM];   // x @ W_self + bs (fully rewritten each call)
__device__ float g_deg[N_NODES];                // in-degree; self-zeroed by final_kernel
__device__ __align__(16) float2 g_Bp[64 * 64];  // k-pair-packed B: kp<32 = W_msg, kp>=32 = W_self
__device__ float g_bm[DIM];
__device__ float g_bs[DIM];

// packed f32x2 FMA: d.lo += a.lo*b.lo ; d.hi += a.hi*b.hi
__device__ __forceinline__ void fma2(unsigned long long& d,
                                     unsigned long long a,
                                     unsigned long long b) {
    asm("fma.rn.f32x2 %0, %1, %2, %0;" : "+l"(d) : "l"(a), "l"(b));
}
__device__ __forceinline__ float pair_sum(unsigned long long v) {
    return __uint_as_float((unsigned)(v & 0xffffffffull)) +
           __uint_as_float((unsigned)(v >> 32));
}

// ---------------- kernel 1: collapse bases into packed weights (~5us) ------
__global__ __launch_bounds__(256) void build_weights(
    const float* __restrict__ wm, const float* __restrict__ bm,
    const float* __restrict__ ws, const float* __restrict__ bs,
    const float* __restrict__ lc) {
    __shared__ float c[NBASES];
    if (threadIdx.x < NBASES) c[threadIdx.x] = lc[threadIdx.x];
    __syncthreads();
    if (blockIdx.x < 16) {
        int idx = blockIdx.x * 256 + threadIdx.x;   // 0..4095
        int kp = idx >> 6;
        int o  = idx & 63;
        const float* base = (kp < 32) ? wm : ws;
        int i0 = (kp < 32) ? 2 * kp : 2 * (kp - 32);
        const float4* p0 = reinterpret_cast<const float4*>(&base[((size_t)i0 * 64 + o) * NBASES]);
        const float4* p1 = reinterpret_cast<const float4*>(&base[((size_t)(i0 + 1) * 64 + o) * NBASES]);
        float lo = 0.f, hi = 0.f;
        #pragma unroll
        for (int q = 0; q < 4; q++) {
            float4 a0 = __ldg(&p0[q]);
            float4 a1 = __ldg(&p1[q]);
            lo = fmaf(a0.x, c[4*q+0], lo); lo = fmaf(a0.y, c[4*q+1], lo);
            lo = fmaf(a0.z, c[4*q+2], lo); lo = fmaf(a0.w, c[4*q+3], lo);
            hi = fmaf(a1.x, c[4*q+0], hi); hi = fmaf(a1.y, c[4*q+1], hi);
            hi = fmaf(a1.z, c[4*q+2], hi); hi = fmaf(a1.w, c[4*q+3], hi);
        }
        g_Bp[idx] = make_float2(lo, hi);
    } else if (threadIdx.x < DIM) {
        int t = threadIdx.x;
        float am = 0.f, as = 0.f;
        #pragma unroll
        for (int b = 0; b < NBASES; b++) {
            am = fmaf(__ldg(&bm[t * NBASES + b]), c[b], am);
            as = fmaf(__ldg(&bs[t * NBASES + b]), c[b], as);
        }
        g_bm[t] = am;
        g_bs[t] = as;
    }
}

// ---------------- kernel 2: OVERLAPPED scatter + xself GEMM ----------------
// Every 26th block: xself tile (64 nodes, K=64, x @ W_self + bs -> g_Xs).
// Other blocks: edge scatter (R5-proven ILP-2 red.v4).
// The two block types bind different pipes (FMA vs L2-atomic ALU), so they
// co-run: predicted max(52us scatter, ~48us gemm) instead of their sum.
__global__ __launch_bounds__(256) void mid_kernel(
    const float* __restrict__ x, const int* __restrict__ ei) {
    const int bid = blockIdx.x;
    const int tid = threadIdx.x;

    if (bid % GEMM_STRIDE == 0) {
        // ===== xself GEMM block =====
        const int tile = bid / GEMM_STRIDE;            // 0..1562
        const int jj = tid & 15;
        const int nn = tid >> 4;
        const int j0 = jj * 4;
        const int n0 = nn * 4;
        const int node0 = tile * 64;

        const ulonglong2* __restrict__ X2  = reinterpret_cast<const ulonglong2*>(x);
        const ulonglong2* __restrict__ Bp2 = reinterpret_cast<const ulonglong2*>(g_Bp);
        const int bbase = j0 >> 1;

        int node[4];
        #pragma unroll
        for (int r = 0; r < 4; r++)
            node[r] = min(node0 + n0 + r, N_NODES - 1);  // clamp; no shuffles here

        unsigned long long acc[4][4];
        #pragma unroll
        for (int r = 0; r < 4; r++)
            #pragma unroll
            for (int c2 = 0; c2 < 4; c2++) acc[r][c2] = 0ull;

        #pragma unroll 4
        for (int k4 = 0; k4 < 16; k4++) {
            ulonglong2 av[4];
            #pragma unroll
            for (int r = 0; r < 4; r++)
                av[r] = __ldg(&X2[(size_t)node[r] * 16 + k4]);
            #pragma unroll
            for (int p = 0; p < 2; p++) {
                int kp = 32 + k4 * 2 + p;              // W_self pair-rows
                ulonglong2 b01 = __ldg(&Bp2[kp * 32 + bbase]);
                ulonglong2 b23 = __ldg(&Bp2[kp * 32 + bbase + 1]);
                #pragma unroll
                for (int r = 0; r < 4; r++) {
                    unsigned long long a = p ? av[r].y : av[r].x;
                    fma2(acc[r][0], a, b01.x);
                    fma2(acc[r][1], a, b01.y);
                    fma2(acc[r][2], a, b23.x);
                    fma2(acc[r][3], a, b23.y);
                }
            }
        }

        float bsj[4];
        #pragma unroll
        for (int c = 0; c < 4; c++) bsj[c] = __ldg(&g_bs[j0 + c]);

        float4* Xs4 = reinterpret_cast<float4*>(g_Xs);
        #pragma unroll
        for (int r = 0; r < 4; r++) {
            if (node0 + n0 + r < N_NODES) {
                float4 ov = make_float4(pair_sum(acc[r][0]) + bsj[0],
                                        pair_sum(acc[r][1]) + bsj[1],
                                        pair_sum(acc[r][2]) + bsj[2],
                                        pair_sum(acc[r][3]) + bsj[3]);
                Xs4[(size_t)node[r] * 16 + jj] = ov;
            }
        }
    } else {
        // ===== scatter block =====
        // scatter-block index = bid minus the GEMM blocks before it
        const int sbid = bid - 1 - (bid - 1) / GEMM_STRIDE;
        int t = sbid * 256 + tid;
        int e = t >> 4;
        if (e >= E_HALF) return;
        int sub = t & 15;
        int e2 = e + E_HALF;
        int src1 = __ldg(&ei[e]);
        int dst1 = __ldg(&ei[N_EDGES + e]);
        int src2 = __ldg(&ei[e2]);
        int dst2 = __ldg(&ei[N_EDGES + e2]);
        const float4* x4 = reinterpret_cast<const float4*>(x);
        float4 v1 = __ldg(&x4[(size_t)src1 * 16 + sub]);
        float4 v2 = __ldg(&x4[(size_t)src2 * 16 + sub]);
        float* p1 = &g_S[(size_t)dst1 * DIM + sub * 4];
        float* p2 = &g_S[(size_t)dst2 * DIM + sub * 4];
        asm volatile("red.global.add.v4.f32 [%0], {%1, %2, %3, %4};"
                     :: "l"(p1), "f"(v1.x), "f"(v1.y), "f"(v1.z), "f"(v1.w) : "memory");
        asm volatile("red.global.add.v4.f32 [%0], {%1, %2, %3, %4};"
                     :: "l"(p2), "f"(v2.x), "f"(v2.y), "f"(v2.z), "f"(v2.w) : "memory");
        if (sub == 0) {
            atomicAdd(&g_deg[dst1], 1.0f);
            atomicAdd(&g_deg[dst2], 1.0f);
        }
    }
}

// ---------------- kernel 3: out = S@W_msg + deg*bm + xself, L2-norm --------
// K=64 only (half the FMAs of the old 93us full-K kernel). Self-cleans
// g_S/g_deg for the next launch (proven ordering: shuffle reduction happens
// after all lanes' reads, before the jj==0 cleanup stores).
__global__ __launch_bounds__(256) void final_kernel(float* __restrict__ out) {
    const int tid = threadIdx.x;
    const int jj = tid & 15;
    const int nn = tid >> 4;
    const int j0 = jj * 4;
    const int n0 = nn * 4;
    const int node0 = blockIdx.x * 64;

    const ulonglong2* __restrict__ S2  = reinterpret_cast<const ulonglong2*>(g_S);
    const ulonglong2* __restrict__ Bp2 = reinterpret_cast<const ulonglong2*>(g_Bp);
    const int bbase = j0 >> 1;

    int node[4];
    #pragma unroll
    for (int r = 0; r < 4; r++)
        node[r] = min(node0 + n0 + r, N_NODES - 1);  // clamp; uniform per 16-lane group

    unsigned long long acc[4][4];
    #pragma unroll
    for (int r = 0; r < 4; r++)
        #pragma unroll
        for (int c2 = 0; c2 < 4; c2++) acc[r][c2] = 0ull;

    #pragma unroll 4
    for (int k4 = 0; k4 < 16; k4++) {
        ulonglong2 av[4];
        #pragma unroll
        for (int r = 0; r < 4; r++)
            av[r] = __ldg(&S2[(size_t)node[r] * 16 + k4]);
        #pragma unroll
        for (int p = 0; p < 2; p++) {
            int kp = k4 * 2 + p;                       // W_msg pair-rows
            ulonglong2 b01 = __ldg(&Bp2[kp * 32 + bbase]);
            ulonglong2 b23 = __ldg(&Bp2[kp * 32 + bbase + 1]);
            #pragma unroll
            for (int r = 0; r < 4; r++) {
                unsigned long long a = p ? av[r].y : av[r].x;
                fma2(acc[r][0], a, b01.x);
                fma2(acc[r][1], a, b01.y);
                fma2(acc[r][2], a, b23.x);
                fma2(acc[r][3], a, b23.y);
            }
        }
    }

    float bmj[4];
    #pragma unroll
    for (int c = 0; c < 4; c++) bmj[c] = __ldg(&g_bm[j0 + c]);

    const float4* __restrict__ Xs4 = reinterpret_cast<const float4*>(g_Xs);
    float4* S4 = reinterpret_cast<float4*>(g_S);

    #pragma unroll
    for (int r = 0; r < 4; r++) {
        const bool valid = (node0 + n0 + r < N_NODES);
        float deg = __ldg(&g_deg[node[r]]);
        float4 xs = __ldg(&Xs4[(size_t)node[r] * 16 + jj]);
        float o[4];
        o[0] = pair_sum(acc[r][0]) + deg * bmj[0] + xs.x;
        o[1] = pair_sum(acc[r][1]) + deg * bmj[1] + xs.y;
        o[2] = pair_sum(acc[r][2]) + deg * bmj[2] + xs.z;
        o[3] = pair_sum(acc[r][3]) + deg * bmj[3] + xs.w;
        float ss = o[0] * o[0] + o[1] * o[1] + o[2] * o[2] + o[3] * o[3];
        #pragma unroll
        for (int off = 8; off > 0; off >>= 1)
            ss += __shfl_xor_sync(0xffffffffu, ss, off);   // within 16-lane half
        float inv = 1.0f / fmaxf(sqrtf(ss), 1e-12f);
        if (valid) {
            float4 ov = make_float4(o[0] * inv, o[1] * inv, o[2] * inv, o[3] * inv);
            reinterpret_cast<float4*>(out)[(size_t)node[r] * 16 + jj] = ov;
            // Self-clean: all lanes' reads of this row preceded the shuffle.
            S4[(size_t)node[r] * 16 + jj] = make_float4(0.f, 0.f, 0.f, 0.f);
            if (jj == 0) g_deg[node[r]] = 0.f;
        }
    }
}

// ---------------- launch ----------------------------------------------------
extern "C" void kernel_launch(void* const* d_in, const int* in_sizes, int n_in,
                              void* d_out, int out_size) {
    const float* x  = (const float*)d_in[0];
    const int*   ei = (const int*)d_in[1];
    const float* wm = (const float*)d_in[2];
    const float* bm = (const float*)d_in[3];
    const float* ws = (const float*)d_in[4];
    const float* bs = (const float*)d_in[5];
    const float* lc = (const float*)d_in[6];
    float* out = (float*)d_out;

    // collapse bases into packed weights
    build_weights<<<17, 256>>>(wm, bm, ws, bs, lc);
    // overlapped: edge scatter + xself GEMM (disjoint pipes)
    mid_kernel<<<MID_BLOCKS, 256>>>(x, ei);
    // S@W_msg + deg*bm + xself, normalize, self-clean
    final_kernel<<<N_TILES, 256>>>(out);
}

// round 16
// speedup vs baseline: 1.3886x; 1.3886x over previous
#include <cuda_runtime.h>
#include <cstdint>

#define N_NODES 100000
#define N_EDGES 1250000
#define DIM 64
#define NBASES 16
#define E_HALF (N_EDGES / 2)
#define N_TILES ((N_NODES + 63) / 64)   // 1563

// ---------------- scratch (device globals; no allocation allowed) ----------
// g_S padded by 64 rows so the last tile's 16KB bulk read stays in bounds.
__device__ float g_S[(size_t)(N_NODES + 64) * DIM];  // scatter-sum; self-zeroed by out_kernel
__device__ float g_deg[N_NODES];                     // in-degree; self-zeroed by out_kernel
__device__ __align__(16) float2 g_Bp[64 * 64];       // k-pair-packed B: [kp][c]=(B[2kp][c],B[2kp+1][c])
__device__ float g_bm[DIM];
__device__ float g_bs[DIM];

// packed f32x2 FMA: d.lo += a.lo*b.lo ; d.hi += a.hi*b.hi
__device__ __forceinline__ void fma2(unsigned long long& d,
                                     unsigned long long a,
                                     unsigned long long b) {
    asm("fma.rn.f32x2 %0, %1, %2, %0;" : "+l"(d) : "l"(a), "l"(b));
}
__device__ __forceinline__ float pair_sum(unsigned long long v) {
    return __uint_as_float((unsigned)(v & 0xffffffffull)) +
           __uint_as_float((unsigned)(v >> 32));
}
__device__ __forceinline__ unsigned smem_u32(const void* p) {
    return (unsigned)__cvta_generic_to_shared(p);
}

// ---------------- kernel 1: collapse bases into packed weights (~5us) ------
__global__ __launch_bounds__(256) void build_weights(
    const float* __restrict__ wm, const float* __restrict__ bm,
    const float* __restrict__ ws, const float* __restrict__ bs,
    const float* __restrict__ lc) {
    __shared__ float c[NBASES];
    if (threadIdx.x < NBASES) c[threadIdx.x] = lc[threadIdx.x];
    __syncthreads();
    if (blockIdx.x < 16) {
        int idx = blockIdx.x * 256 + threadIdx.x;   // 0..4095
        int kp = idx >> 6;
        int o  = idx & 63;
        const float* base = (kp < 32) ? wm : ws;
        int i0 = (kp < 32) ? 2 * kp : 2 * (kp - 32);
        const float4* p0 = reinterpret_cast<const float4*>(&base[((size_t)i0 * 64 + o) * NBASES]);
        const float4* p1 = reinterpret_cast<const float4*>(&base[((size_t)(i0 + 1) * 64 + o) * NBASES]);
        float lo = 0.f, hi = 0.f;
        #pragma unroll
        for (int q = 0; q < 4; q++) {
            float4 a0 = __ldg(&p0[q]);
            float4 a1 = __ldg(&p1[q]);
            lo = fmaf(a0.x, c[4*q+0], lo); lo = fmaf(a0.y, c[4*q+1], lo);
            lo = fmaf(a0.z, c[4*q+2], lo); lo = fmaf(a0.w, c[4*q+3], lo);
            hi = fmaf(a1.x, c[4*q+0], hi); hi = fmaf(a1.y, c[4*q+1], hi);
            hi = fmaf(a1.z, c[4*q+2], hi); hi = fmaf(a1.w, c[4*q+3], hi);
        }
        g_Bp[idx] = make_float2(lo, hi);
    } else if (threadIdx.x < DIM) {
        int t = threadIdx.x;
        float am = 0.f, as = 0.f;
        #pragma unroll
        for (int b = 0; b < NBASES; b++) {
            am = fmaf(__ldg(&bm[t * NBASES + b]), c[b], am);
            as = fmaf(__ldg(&bs[t * NBASES + b]), c[b], as);
        }
        g_bm[t] = am;
        g_bs[t] = as;
    }
}

// ---------------- kernel 2: edge scatter (R5-proven, ~52us) ----------------
__global__ __launch_bounds__(256) void edge_scatter(
    const float4* __restrict__ x4, const int* __restrict__ ei) {
    int t = blockIdx.x * blockDim.x + threadIdx.x;
    int e = t >> 4;
    if (e >= E_HALF) return;
    int sub = t & 15;
    int e2 = e + E_HALF;
    int src1 = __ldg(&ei[e]);
    int dst1 = __ldg(&ei[N_EDGES + e]);
    int src2 = __ldg(&ei[e2]);
    int dst2 = __ldg(&ei[N_EDGES + e2]);
    float4 v1 = __ldg(&x4[(size_t)src1 * 16 + sub]);
    float4 v2 = __ldg(&x4[(size_t)src2 * 16 + sub]);
    float* p1 = &g_S[(size_t)dst1 * DIM + sub * 4];
    float* p2 = &g_S[(size_t)dst2 * DIM + sub * 4];
    asm volatile("red.global.add.v4.f32 [%0], {%1, %2, %3, %4};"
                 :: "l"(p1), "f"(v1.x), "f"(v1.y), "f"(v1.z), "f"(v1.w) : "memory");
    asm volatile("red.global.add.v4.f32 [%0], {%1, %2, %3, %4};"
                 :: "l"(p2), "f"(v2.x), "f"(v2.y), "f"(v2.z), "f"(v2.w) : "memory");
    if (sub == 0) {
        atomicAdd(&g_deg[dst1], 1.0f);
        atomicAdd(&g_deg[dst2], 1.0f);
    }
}

// ---------------- kernel 3: out = [S|x] @ [Wm;Ws] + deg*bm + bs, L2-norm ---
// A tiles (S, x — each a CONTIGUOUS 16KB region per 64-node tile) arrive via
// cp.async.bulk + mbarrier: removes the 16-warp LDG front-batch that inflates
// effective latency via cross-CTA L1tex-queue contention (spr_max model).
// The single async wait overlaps with the co-resident block's compute phase.
// Inner loop: A via broadcast LDS, B via __ldg (L1-resident), f32x2 math,
// 4 rows x 4 cols per thread. Self-cleans g_S (early, post-wait) and g_deg.
__global__ __launch_bounds__(256) void out_kernel(const float* __restrict__ x,
                                                  float* __restrict__ out) {
    __shared__ __align__(16) float sS[64 * 64];   // 16KB staged S tile
    __shared__ __align__(16) float sX[64 * 64];   // 16KB staged x tile
    __shared__ __align__(8) unsigned long long mbar;

    const int tid = threadIdx.x;
    const int node0 = blockIdx.x * 64;
    const int rows = min(64, N_NODES - node0);    // 64, except last tile (32)
    const unsigned bytes = (unsigned)rows * 256u;

    const unsigned mb = smem_u32(&mbar);
    if (tid == 0)
        asm volatile("mbarrier.init.shared.b64 [%0], 1;" :: "r"(mb) : "memory");
    __syncthreads();
    if (tid == 0) {
        asm volatile("mbarrier.arrive.expect_tx.shared.b64 _, [%0], %1;"
                     :: "r"(mb), "r"(2u * bytes) : "memory");
        asm volatile("cp.async.bulk.shared::cta.global.mbarrier::complete_tx::bytes "
                     "[%0], [%1], %2, [%3];"
                     :: "r"(smem_u32(sS)), "l"(&g_S[(size_t)node0 * DIM]),
                        "r"(bytes), "r"(mb) : "memory");
        asm volatile("cp.async.bulk.shared::cta.global.mbarrier::complete_tx::bytes "
                     "[%0], [%1], %2, [%3];"
                     :: "r"(smem_u32(sX)), "l"(&x[(size_t)node0 * DIM]),
                        "r"(bytes), "r"(mb) : "memory");
    }
    // All threads wait for both tiles (phase parity 0; single use per block).
    {
        unsigned done;
        do {
            asm volatile("{\n\t.reg .pred p;\n\t"
                         "mbarrier.try_wait.parity.shared.b64 p, [%1], 0;\n\t"
                         "selp.b32 %0, 1, 0, p;\n\t}"
                         : "=r"(done) : "r"(mb) : "memory");
        } while (!done);
    }

    // Early self-clean of this tile's g_S rows (data is safely staged in smem).
    {
        float4* S4g = reinterpret_cast<float4*>(&g_S[(size_t)node0 * DIM]);
        const float4 z4 = make_float4(0.f, 0.f, 0.f, 0.f);
        for (int i = tid; i < rows * 16; i += 256) S4g[i] = z4;
    }

    const int jj = tid & 15;   // column group: cols j0..j0+3
    const int nn = tid >> 4;   // row group:   rows n0..n0+3 (tile-local)
    const int j0 = jj * 4;
    const int n0 = nn * 4;

    const ulonglong2* sS2 = reinterpret_cast<const ulonglong2*>(sS);  // 16 ull2/row
    const ulonglong2* sX2 = reinterpret_cast<const ulonglong2*>(sX);
    const ulonglong2* __restrict__ Bp2 = reinterpret_cast<const ulonglong2*>(g_Bp);
    const int bbase = j0 >> 1;  // ull2 index within a Bp row (32 ull2/row)

    unsigned long long acc[4][4];
    #pragma unroll
    for (int r = 0; r < 4; r++)
        #pragma unroll
        for (int c2 = 0; c2 < 4; c2++) acc[r][c2] = 0ull;

    // ---- K half 1: A = staged S rows (k 0..63), B pair-rows kp 0..31 ----
    #pragma unroll 4
    for (int k4 = 0; k4 < 16; k4++) {
        ulonglong2 av[4];
        #pragma unroll
        for (int r = 0; r < 4; r++)
            av[r] = sS2[(n0 + r) * 16 + k4];
        #pragma unroll
        for (int p = 0; p < 2; p++) {
            int kp = k4 * 2 + p;
            ulonglong2 b01 = __ldg(&Bp2[kp * 32 + bbase]);
            ulonglong2 b23 = __ldg(&Bp2[kp * 32 + bbase + 1]);
            #pragma unroll
            for (int r = 0; r < 4; r++) {
                unsigned long long a = p ? av[r].y : av[r].x;
                fma2(acc[r][0], a, b01.x);
                fma2(acc[r][1], a, b01.y);
                fma2(acc[r][2], a, b23.x);
                fma2(acc[r][3], a, b23.y);
            }
        }
    }
    // ---- K half 2: A = staged x rows (k 64..127), B pair-rows kp 32..63 ----
    #pragma unroll 4
    for (int k4 = 0; k4 < 16; k4++) {
        ulonglong2 av[4];
        #pragma unroll
        for (int r = 0; r < 4; r++)
            av[r] = sX2[(n0 + r) * 16 + k4];
        #pragma unroll
        for (int p = 0; p < 2; p++) {
            int kp = 32 + k4 * 2 + p;
            ulonglong2 b01 = __ldg(&Bp2[kp * 32 + bbase]);
            ulonglong2 b23 = __ldg(&Bp2[kp * 32 + bbase + 1]);
            #pragma unroll
            for (int r = 0; r < 4; r++) {
                unsigned long long a = p ? av[r].y : av[r].x;
                fma2(acc[r][0], a, b01.x);
                fma2(acc[r][1], a, b01.y);
                fma2(acc[r][2], a, b23.x);
                fma2(acc[r][3], a, b23.y);
            }
        }
    }

    // biases for this thread's 4 columns
    float bmj[4], bsj[4];
    #pragma unroll
    for (int c = 0; c < 4; c++) {
        bmj[c] = __ldg(&g_bm[j0 + c]);
        bsj[c] = __ldg(&g_bs[j0 + c]);
    }

    // Epilogue: fold halves, bias, row L2-norm (across 16 jj lanes), store,
    // then zero g_deg (ordering: deg reads precede the shuffle).
    #pragma unroll
    for (int r = 0; r < 4; r++) {
        const int node = node0 + n0 + r;
        const bool valid = (node < N_NODES);
        const int nodec = min(node, N_NODES - 1);
        float deg = __ldg(&g_deg[nodec]);
        float o[4];
        #pragma unroll
        for (int c = 0; c < 4; c++)
            o[c] = pair_sum(acc[r][c]) + deg * bmj[c] + bsj[c];
        float ss = o[0] * o[0] + o[1] * o[1] + o[2] * o[2] + o[3] * o[3];
        #pragma unroll
        for (int off = 8; off > 0; off >>= 1)
            ss += __shfl_xor_sync(0xffffffffu, ss, off);   // within 16-lane half
        float inv = 1.0f / fmaxf(sqrtf(ss), 1e-12f);
        if (valid) {
            float4 ov = make_float4(o[0] * inv, o[1] * inv, o[2] * inv, o[3] * inv);
            reinterpret_cast<float4*>(out)[(size_t)node * 16 + jj] = ov;
            if (jj == 0) g_deg[node] = 0.f;    // after shuffle = after all reads
        }
    }
}

// ---------------- launch ----------------------------------------------------
extern "C" void kernel_launch(void* const* d_in, const int* in_sizes, int n_in,
                              void* d_out, int out_size) {
    const float* x  = (const float*)d_in[0];
    const int*   ei = (const int*)d_in[1];
    const float* wm = (const float*)d_in[2];
    const float* bm = (const float*)d_in[3];
    const float* ws = (const float*)d_in[4];
    const float* bs = (const float*)d_in[5];
    const float* lc = (const float*)d_in[6];
    float* out = (float*)d_out;

    // collapse bases into packed weights
    build_weights<<<17, 256>>>(wm, bm, ws, bs, lc);
    // edge scatter (g_S/g_deg zero: BSS on first call, self-cleaned after)
    {
        long long tot = (long long)E_HALF * 16;            // 10M threads
        int blocks = (int)((tot + 255) / 256);
        edge_scatter<<<blocks, 256>>>((const float4*)x, ei);
    }
    // fused GEMM + bias + normalize + self-clean (bulk-copy staged A tiles)
    out_kernel<<<N_TILES, 256>>>(x, out);
}

// round 17
// speedup vs baseline: 1.3910x; 1.0017x over previous
#include <cuda_runtime.h>
#include <cstdint>

#define N_NODES 100000
#define N_EDGES 1250000
#define DIM 64
#define NBASES 16
#define E_HALF (N_EDGES / 2)
#define N_TILES ((N_NODES + 63) / 64)   // 1563
#define GRID_OUT 296                    // 2 blocks/SM persistent
#define BUF_BYTES 16384                 // one 64x64 f32 tile
#define SMEM_TOTAL (4 * BUF_BYTES + 32) // 2 stages x (S,X) + mbarriers

// ---------------- scratch (device globals; no allocation allowed) ----------
// g_S padded by 64 rows so the last tile's bulk read stays in bounds.
__device__ float g_S[(size_t)(N_NODES + 64) * DIM];  // scatter-sum; self-zeroed by out_kernel
__device__ float g_deg[N_NODES];                     // in-degree; self-zeroed by out_kernel
__device__ __align__(16) float2 g_Bp[64 * 64];       // k-pair-packed B
__device__ float g_bm[DIM];
__device__ float g_bs[DIM];

__device__ __forceinline__ void fma2(unsigned long long& d,
                                     unsigned long long a,
                                     unsigned long long b) {
    asm("fma.rn.f32x2 %0, %1, %2, %0;" : "+l"(d) : "l"(a), "l"(b));
}
__device__ __forceinline__ float pair_sum(unsigned long long v) {
    return __uint_as_float((unsigned)(v & 0xffffffffull)) +
           __uint_as_float((unsigned)(v >> 32));
}
__device__ __forceinline__ unsigned smem_u32(const void* p) {
    return (unsigned)__cvta_generic_to_shared(p);
}
__device__ __forceinline__ void bulk_copy(unsigned dst, const void* src,
                                          unsigned bytes, unsigned mb) {
    asm volatile("cp.async.bulk.shared::cta.global.mbarrier::complete_tx::bytes "
                 "[%0], [%1], %2, [%3];"
                 :: "r"(dst), "l"(src), "r"(bytes), "r"(mb) : "memory");
}
__device__ __forceinline__ void mbar_wait(unsigned mb, unsigned parity) {
    unsigned done;
    do {
        asm volatile("{\n\t.reg .pred p;\n\t"
                     "mbarrier.try_wait.parity.shared.b64 p, [%1], %2;\n\t"
                     "selp.b32 %0, 1, 0, p;\n\t}"
                     : "=r"(done) : "r"(mb), "r"(parity) : "memory");
    } while (!done);
}

// ---------------- kernel 1: collapse bases into packed weights (~5us) ------
__global__ __launch_bounds__(256) void build_weights(
    const float* __restrict__ wm, const float* __restrict__ bm,
    const float* __restrict__ ws, const float* __restrict__ bs,
    const float* __restrict__ lc) {
    __shared__ float c[NBASES];
    if (threadIdx.x < NBASES) c[threadIdx.x] = lc[threadIdx.x];
    __syncthreads();
    if (blockIdx.x < 16) {
        int idx = blockIdx.x * 256 + threadIdx.x;
        int kp = idx >> 6;
        int o  = idx & 63;
        const float* base = (kp < 32) ? wm : ws;
        int i0 = (kp < 32) ? 2 * kp : 2 * (kp - 32);
        const float4* p0 = reinterpret_cast<const float4*>(&base[((size_t)i0 * 64 + o) * NBASES]);
        const float4* p1 = reinterpret_cast<const float4*>(&base[((size_t)(i0 + 1) * 64 + o) * NBASES]);
        float lo = 0.f, hi = 0.f;
        #pragma unroll
        for (int q = 0; q < 4; q++) {
            float4 a0 = __ldg(&p0[q]);
            float4 a1 = __ldg(&p1[q]);
            lo = fmaf(a0.x, c[4*q+0], lo); lo = fmaf(a0.y, c[4*q+1], lo);
            lo = fmaf(a0.z, c[4*q+2], lo); lo = fmaf(a0.w, c[4*q+3], lo);
            hi = fmaf(a1.x, c[4*q+0], hi); hi = fmaf(a1.y, c[4*q+1], hi);
            hi = fmaf(a1.z, c[4*q+2], hi); hi = fmaf(a1.w, c[4*q+3], hi);
        }
        g_Bp[idx] = make_float2(lo, hi);
    } else if (threadIdx.x < DIM) {
        int t = threadIdx.x;
        float am = 0.f, as = 0.f;
        #pragma unroll
        for (int b = 0; b < NBASES; b++) {
            am = fmaf(__ldg(&bm[t * NBASES + b]), c[b], am);
            as = fmaf(__ldg(&bs[t * NBASES + b]), c[b], as);
        }
        g_bm[t] = am;
        g_bs[t] = as;
    }
}

// ---------------- kernel 2: edge scatter (R5-proven, ~52us) ----------------
__global__ __launch_bounds__(256) void edge_scatter(
    const float4* __restrict__ x4, const int* __restrict__ ei) {
    int t = blockIdx.x * blockDim.x + threadIdx.x;
    int e = t >> 4;
    if (e >= E_HALF) return;
    int sub = t & 15;
    int e2 = e + E_HALF;
    int src1 = __ldg(&ei[e]);
    int dst1 = __ldg(&ei[N_EDGES + e]);
    int src2 = __ldg(&ei[e2]);
    int dst2 = __ldg(&ei[N_EDGES + e2]);
    float4 v1 = __ldg(&x4[(size_t)src1 * 16 + sub]);
    float4 v2 = __ldg(&x4[(size_t)src2 * 16 + sub]);
    float* p1 = &g_S[(size_t)dst1 * DIM + sub * 4];
    float* p2 = &g_S[(size_t)dst2 * DIM + sub * 4];
    asm volatile("red.global.add.v4.f32 [%0], {%1, %2, %3, %4};"
                 :: "l"(p1), "f"(v1.x), "f"(v1.y), "f"(v1.z), "f"(v1.w) : "memory");
    asm volatile("red.global.add.v4.f32 [%0], {%1, %2, %3, %4};"
                 :: "l"(p2), "f"(v2.x), "f"(v2.y), "f"(v2.z), "f"(v2.w) : "memory");
    if (sub == 0) {
        atomicAdd(&g_deg[dst1], 1.0f);
        atomicAdd(&g_deg[dst2], 1.0f);
    }
}

// ---------------- kernel 3: PERSISTENT double-buffered GEMM ----------------
// 296 blocks, each walks tiles bid, bid+296, ... While computing tile i from
// stage i&1, the bulk copies for tile i+1 are in flight into the other stage.
// Attacks the R2/R5/R16-invariant 93us: S/x come from DRAM (L2-evicted by
// the scatter), and without pipelining each block serialized copy->compute.
// Inner loop identical to R16 (proven): A via LDS, B via __ldg, f32x2 math.
__global__ __launch_bounds__(256) void out_kernel(const float* __restrict__ x,
                                                  float* __restrict__ out) {
    extern __shared__ __align__(16) char dsm[];
    float* sS[2] = { (float*)(dsm),
                     (float*)(dsm + 2 * BUF_BYTES) };
    float* sX[2] = { (float*)(dsm + BUF_BYTES),
                     (float*)(dsm + 3 * BUF_BYTES) };
    unsigned mb[2] = { smem_u32(dsm + 4 * BUF_BYTES),
                       smem_u32(dsm + 4 * BUF_BYTES + 8) };

    const int tid = threadIdx.x;
    if (tid == 0) {
        asm volatile("mbarrier.init.shared.b64 [%0], 1;" :: "r"(mb[0]) : "memory");
        asm volatile("mbarrier.init.shared.b64 [%0], 1;" :: "r"(mb[1]) : "memory");
    }
    __syncthreads();

    // prolog: copy first tile into stage 0
    if (tid == 0) {
        int t0 = blockIdx.x;
        unsigned bytes = (unsigned)min(64, N_NODES - t0 * 64) * 256u;
        asm volatile("mbarrier.arrive.expect_tx.shared.b64 _, [%0], %1;"
                     :: "r"(mb[0]), "r"(2u * bytes) : "memory");
        bulk_copy(smem_u32(sS[0]), &g_S[(size_t)t0 * 64 * DIM], bytes, mb[0]);
        bulk_copy(smem_u32(sX[0]), &x[(size_t)t0 * 64 * DIM], bytes, mb[0]);
    }

    const int jj = tid & 15;
    const int nn = tid >> 4;
    const int j0 = jj * 4;
    const int n0 = nn * 4;
    const ulonglong2* __restrict__ Bp2 = reinterpret_cast<const ulonglong2*>(g_Bp);
    const int bbase = j0 >> 1;

    float bmj[4], bsj[4];
    #pragma unroll
    for (int c = 0; c < 4; c++) {
        bmj[c] = __ldg(&g_bm[j0 + c]);
        bsj[c] = __ldg(&g_bs[j0 + c]);
    }

    int ph[2] = {0, 0};
    int i = 0;
    for (int t = blockIdx.x; t < N_TILES; t += GRID_OUT, i++) {
        const int b = i & 1;
        const int node0 = t * 64;

        // prefetch next tile into the other stage (free since end of iter i-1)
        const int tn = t + GRID_OUT;
        if (tid == 0 && tn < N_TILES) {
            unsigned bytes = (unsigned)min(64, N_NODES - tn * 64) * 256u;
            asm volatile("mbarrier.arrive.expect_tx.shared.b64 _, [%0], %1;"
                         :: "r"(mb[1 - b]), "r"(2u * bytes) : "memory");
            bulk_copy(smem_u32(sS[1 - b]), &g_S[(size_t)tn * 64 * DIM], bytes, mb[1 - b]);
            bulk_copy(smem_u32(sX[1 - b]), &x[(size_t)tn * 64 * DIM], bytes, mb[1 - b]);
        }

        // wait for current stage
        mbar_wait(mb[b], ph[b]);
        ph[b] ^= 1;

        const int rows = min(64, N_NODES - node0);
        // early self-clean of this tile's g_S rows (data staged in smem)
        {
            float4* S4g = reinterpret_cast<float4*>(&g_S[(size_t)node0 * DIM]);
            const float4 z4 = make_float4(0.f, 0.f, 0.f, 0.f);
            for (int v = tid; v < rows * 16; v += 256) S4g[v] = z4;
        }

        const ulonglong2* sS2 = reinterpret_cast<const ulonglong2*>(sS[b]);
        const ulonglong2* sX2 = reinterpret_cast<const ulonglong2*>(sX[b]);

        unsigned long long acc[4][4];
        #pragma unroll
        for (int r = 0; r < 4; r++)
            #pragma unroll
            for (int c2 = 0; c2 < 4; c2++) acc[r][c2] = 0ull;

        // K half 1: A = staged S rows, B pair-rows kp 0..31
        #pragma unroll 4
        for (int k4 = 0; k4 < 16; k4++) {
            ulonglong2 av[4];
            #pragma unroll
            for (int r = 0; r < 4; r++)
                av[r] = sS2[(n0 + r) * 16 + k4];
            #pragma unroll
            for (int p = 0; p < 2; p++) {
                int kp = k4 * 2 + p;
                ulonglong2 b01 = __ldg(&Bp2[kp * 32 + bbase]);
                ulonglong2 b23 = __ldg(&Bp2[kp * 32 + bbase + 1]);
                #pragma unroll
                for (int r = 0; r < 4; r++) {
                    unsigned long long a = p ? av[r].y : av[r].x;
                    fma2(acc[r][0], a, b01.x);
                    fma2(acc[r][1], a, b01.y);
                    fma2(acc[r][2], a, b23.x);
                    fma2(acc[r][3], a, b23.y);
                }
            }
        }
        // K half 2: A = staged x rows, B pair-rows kp 32..63
        #pragma unroll 4
        for (int k4 = 0; k4 < 16; k4++) {
            ulonglong2 av[4];
            #pragma unroll
            for (int r = 0; r < 4; r++)
                av[r] = sX2[(n0 + r) * 16 + k4];
            #pragma unroll
            for (int p = 0; p < 2; p++) {
                int kp = 32 + k4 * 2 + p;
                ulonglong2 b01 = __ldg(&Bp2[kp * 32 + bbase]);
                ulonglong2 b23 = __ldg(&Bp2[kp * 32 + bbase + 1]);
                #pragma unroll
                for (int r = 0; r < 4; r++) {
                    unsigned long long a = p ? av[r].y : av[r].x;
                    fma2(acc[r][0], a, b01.x);
                    fma2(acc[r][1], a, b01.y);
                    fma2(acc[r][2], a, b23.x);
                    fma2(acc[r][3], a, b23.y);
                }
            }
        }

        // Epilogue: fold, bias, row L2-norm (16-lane groups), store, deg clean.
        #pragma unroll
        for (int r = 0; r < 4; r++) {
            const int node = node0 + n0 + r;
            const bool valid = (node < N_NODES);
            const int nodec = min(node, N_NODES - 1);
            float deg = __ldg(&g_deg[nodec]);
            float o[4];
            #pragma unroll
            for (int c = 0; c < 4; c++)
                o[c] = pair_sum(acc[r][c]) + deg * bmj[c] + bsj[c];
            float ss = o[0] * o[0] + o[1] * o[1] + o[2] * o[2] + o[3] * o[3];
            #pragma unroll
            for (int off = 8; off > 0; off >>= 1)
                ss += __shfl_xor_sync(0xffffffffu, ss, off);
            float inv = 1.0f / fmaxf(sqrtf(ss), 1e-12f);
            if (valid) {
                float4 ov = make_float4(o[0] * inv, o[1] * inv, o[2] * inv, o[3] * inv);
                reinterpret_cast<float4*>(out)[(size_t)node * 16 + jj] = ov;
                if (jj == 0) g_deg[node] = 0.f;
            }
        }

        __syncthreads();   // stage b free before iter i+1 prefetches into it
    }
}

// ---------------- launch ----------------------------------------------------
extern "C" void kernel_launch(void* const* d_in, const int* in_sizes, int n_in,
                              void* d_out, int out_size) {
    const float* x  = (const float*)d_in[0];
    const int*   ei = (const int*)d_in[1];
    const float* wm = (const float*)d_in[2];
    const float* bm = (const float*)d_in[3];
    const float* ws = (const float*)d_in[4];
    const float* bs = (const float*)d_in[5];
    const float* lc = (const float*)d_in[6];
    float* out = (float*)d_out;

    build_weights<<<17, 256>>>(wm, bm, ws, bs, lc);
    {
        long long tot = (long long)E_HALF * 16;
        int blocks = (int)((tot + 255) / 256);
        edge_scatter<<<blocks, 256>>>((const float4*)x, ei);
    }
    cudaFuncSetAttribute(out_kernel, cudaFuncAttributeMaxDynamicSharedMemorySize,
                         SMEM_TOTAL);
    out_kernel<<<GRID_OUT, 256, SMEM_TOTAL>>>(x, out);
}